// round 11
// baseline (speedup 1.0000x reference)
#include <cuda_runtime.h>
#include <math.h>

// DiffJPEG forward: persistent fused kernel, OCTET (8 threads) per 8x8 block,
// half-strip tasks for balance, zipped quant tables + fmaf magic rounding.
// img: (16,3,512,512) f32, quality: int scalar, out: (16,3,512,512) f32.

#define IMG_W 512
#define IMG_H 512
#define BATCH 16
#define NTHREADS 768
#define NTASKS 2048                        // batch * 64 strips * 2 halves
#define NRESIDENT 296                      // 148 SMs * 2 CTAs
// 96 units (3 ch * 32 blocks) per half-strip; slot = unit*72 + (a>>2)*36 + (a&3)*8 + b
#define SMEM_FLOATS (96 * 72)              // 6912
#define SMEM_BYTES  (SMEM_FLOATS * 4)      // 27648

#define MAGIC 12582912.0f                  // 1.5 * 2^23: round-to-nearest-even

// Orthonormal 8-pt DCT-II butterfly constants (double-derived)
#define CA  0.35355339059327373f
#define CB1 0.46193976625564337f
#define CB3 0.19134171618254492f
#define CD1 0.49039264020161522f
#define CD3 0.41573480615127262f
#define CD5 0.27778511650980114f
#define CD7 0.09754516100806413f

#define FDCT8(x0,x1,x2,x3,x4,x5,x6,x7) do {                                  \
    float e0=(x0)+(x7), e1=(x1)+(x6), e2=(x2)+(x5), e3=(x3)+(x4);            \
    float o0=(x0)-(x7), o1=(x1)-(x6), o2=(x2)-(x5), o3=(x3)-(x4);            \
    float ee0=e0+e3, ee1=e1+e2, eo0=e0-e3, eo1=e1-e2;                        \
    (x0) = CA*(ee0+ee1);                                                     \
    (x4) = CA*(ee0-ee1);                                                     \
    (x2) = CB1*eo0 + CB3*eo1;                                                \
    (x6) = CB3*eo0 - CB1*eo1;                                                \
    (x1) = CD1*o0 + CD3*o1 + CD5*o2 + CD7*o3;                                \
    (x3) = CD3*o0 - CD7*o1 - CD1*o2 - CD5*o3;                                \
    (x5) = CD5*o0 - CD1*o1 + CD7*o2 + CD3*o3;                                \
    (x7) = CD7*o0 - CD5*o1 + CD3*o2 - CD1*o3;                                \
} while(0)

#define IDCT8(x0,x1,x2,x3,x4,x5,x6,x7) do {                                  \
    float ee0 = CA*((x0)+(x4)), ee1 = CA*((x0)-(x4));                        \
    float eo0 = CB1*(x2) + CB3*(x6), eo1 = CB3*(x2) - CB1*(x6);              \
    float o0 = CD1*(x1) + CD3*(x3) + CD5*(x5) + CD7*(x7);                    \
    float o1 = CD3*(x1) - CD7*(x3) - CD1*(x5) - CD5*(x7);                    \
    float o2 = CD5*(x1) - CD1*(x3) + CD7*(x5) + CD3*(x7);                    \
    float o3 = CD7*(x1) - CD5*(x3) + CD3*(x5) - CD1*(x7);                    \
    float e0=ee0+eo0, e3=ee0-eo0, e1=ee1+eo1, e2=ee1-eo1;                    \
    (x0)=e0+o0; (x7)=e0-o0; (x1)=e1+o1; (x6)=e1-o1;                          \
    (x2)=e2+o2; (x5)=e2-o2; (x3)=e3+o3; (x4)=e3-o3;                          \
} while(0)

__constant__ float c_lum[64] = {
    16, 11, 10, 16, 24, 40, 51, 61,
    12, 12, 14, 19, 26, 58, 60, 55,
    14, 13, 16, 24, 40, 57, 69, 56,
    14, 17, 22, 29, 51, 87, 80, 62,
    18, 22, 37, 56, 68, 109, 103, 77,
    24, 35, 55, 64, 81, 104, 113, 92,
    49, 64, 78, 87, 103, 121, 120, 101,
    72, 92, 95, 98, 112, 100, 103, 99
};
__constant__ float c_chrom[64] = {
    17, 18, 24, 47, 99, 99, 99, 99,
    18, 21, 26, 66, 99, 99, 99, 99,
    24, 26, 56, 99, 99, 99, 99, 99,
    47, 66, 99, 99, 99, 99, 99, 99,
    99, 99, 99, 99, 99, 99, 99, 99,
    99, 99, 99, 99, 99, 99, 99, 99,
    99, 99, 99, 99, 99, 99, 99, 99,
    99, 99, 99, 99, 99, 99, 99, 99
};

__global__ void __launch_bounds__(NTHREADS, 2)
jpeg_kernel(const float* __restrict__ img,
            const int* __restrict__ quality,
            float* __restrict__ out)
{
    extern __shared__ float sm[];
    // zipped quant tables: float4 (q_2kp, 1/q_2kp, q_2kp+1, 1/q_2kp+1) at l*5+kp
    __shared__ __align__(16) float qzipL[160];
    __shared__ __align__(16) float qzipC[160];

    const int tid = threadIdx.x;

    // Build tables ONCE per persistent CTA
    if (tid < 256) {
        int t = tid >> 7;                 // 0 lum, 1 chrom
        int rem = tid & 127;
        int l = rem >> 4;
        int kp = (rem >> 2) & 3;
        int comp = rem & 3;               // 0:q0 1:r0 2:q1 3:r1
        int k = 2 * kp + (comp >> 1);
        int q = *quality;
        q = max(1, min(100, q));
        float scale = (q < 50) ? (5000.0f / (float)q) : (200.0f - 2.0f * (float)q);
        float base = t ? c_chrom[k * 8 + l] : c_lum[k * 8 + l];
        float v = (base * scale + 50.0f) / 100.0f;
        v = fminf(fmaxf(v, 1.0f), 255.0f);
        float outv = (comp & 1) ? (1.0f / v) : v;
        (t ? qzipC : qzipL)[(l * 5 + kp) * 4 + comp] = outv;
    }

    const size_t CH = (size_t)IMG_H * IMG_W;

    // octet decomposition (task-invariant): 8 threads per 8x8 block
    const int unit = tid >> 3;          // 0..95 = c*32 + blk
    const int r = tid & 7;              // my row (and my column after transpose)
    const int c = unit >> 5;            // channel
    float* const ub = sm + unit * 72;
    float* const rp = ub + (r >> 2) * 36 + (r & 3) * 8;   // my row base

    for (int task = blockIdx.x; task < NTASKS; task += NRESIDENT) {
        const int b = task >> 7;
        const int rem = task & 127;
        const int strip = rem >> 1;
        const int halfc = rem & 1;
        const int row0 = strip * 8;
        const int col0 = halfc << 8;          // 0 or 256
        const size_t img_base = (size_t)b * 3 * CH;

        // previous task's Phase C reads done before overwriting smem
        __syncthreads();

        // ---- Phase A: load + RGB->YCbCr (x255 folded); 512 groups ----
        if (tid < 512) {
            int rr = tid >> 6;                 // 0..7
            int cg = tid & 63;                 // float4 group in half-strip
            int col = col0 + (cg << 2);
            size_t off = img_base + (size_t)(row0 + rr) * IMG_W + col;
            float4 r4 = *(const float4*)(img + off);
            float4 g4 = *(const float4*)(img + off + CH);
            float4 b4 = *(const float4*)(img + off + 2 * CH);
            float4 y4, cb4, cr4;
            {
                const float* Rp = &r4.x; const float* Gp = &g4.x; const float* Bp = &b4.x;
                float* Yp = &y4.x; float* Cbp = &cb4.x; float* Crp = &cr4.x;
                #pragma unroll
                for (int j = 0; j < 4; j++) {
                    float R = Rp[j], G = Gp[j], B = Bp[j];
                    Yp[j]  = fmaf(76.245f, R, fmaf(149.685f, G, 29.07f * B));
                    Cbp[j] = fmaf(-43.0185f, R, fmaf(-84.4815f, G, fmaf(127.5f, B, 128.0f)));
                    Crp[j] = fmaf(127.5f, R, fmaf(-106.7685f, G, fmaf(-20.7315f, B, 128.0f)));
                }
            }
            int blk = cg >> 1;
            int sb = blk * 72 + (rr >> 2) * 36 + (rr & 3) * 8 + ((cg & 1) << 2);
            *(float4*)(sm + sb)            = y4;
            *(float4*)(sm + 32 * 72 + sb)  = cb4;
            *(float4*)(sm + 64 * 72 + sb)  = cr4;
        }
        __syncthreads();

        // ---- Phase B: octet per 8x8 block; 1 row / 1 column per thread ----
        {
            float x0,x1,x2,x3,x4,x5,x6,x7;
            // load my spatial row
            {
                float4 v0 = *(const float4*)(rp);
                float4 v1 = *(const float4*)(rp + 4);
                x0=v0.x; x1=v0.y; x2=v0.z; x3=v0.w;
                x4=v1.x; x5=v1.y; x6=v1.z; x7=v1.w;
            }
            FDCT8(x0,x1,x2,x3,x4,x5,x6,x7);

            __syncwarp();
            // T1 store transposed: element (row r, freq l) -> position (l, r)
            ub[0*36 + 0*8 + r] = x0;
            ub[0*36 + 1*8 + r] = x1;
            ub[0*36 + 2*8 + r] = x2;
            ub[0*36 + 3*8 + r] = x3;
            ub[1*36 + 0*8 + r] = x4;
            ub[1*36 + 1*8 + r] = x5;
            ub[1*36 + 2*8 + r] = x6;
            ub[1*36 + 3*8 + r] = x7;
            __syncwarp();

            // load my column l = r (contiguous after transpose)
            float y0,y1,y2,y3,y4,y5,y6,y7;
            {
                float4 v0 = *(const float4*)(rp);
                float4 v1 = *(const float4*)(rp + 4);
                y0=v0.x; y1=v0.y; y2=v0.z; y3=v0.w;
                y4=v1.x; y5=v1.y; y6=v1.z; y7=v1.w;
            }
            FDCT8(y0,y1,y2,y3,y4,y5,y6,y7);   // -> D[k][l=r]

            // -128 input shift commutes to DC only (l==0, k==0)
            if (r == 0) y0 -= 1024.0f;

            // quantize: zipped LDS.128 + fmaf magic round-to-even
            {
                const float* qz = ((b * 3 + c) < BATCH) ? qzipL : qzipC;
                const float4* zl = (const float4*)(qz + r * 20);  // l = r
                float4 z;
                z = zl[0];
                { float t0=fmaf(y0,z.y,MAGIC), t1=fmaf(y1,z.w,MAGIC);
                  y0=__fadd_rn(t0,-MAGIC)*z.x; y1=__fadd_rn(t1,-MAGIC)*z.z; }
                z = zl[1];
                { float t0=fmaf(y2,z.y,MAGIC), t1=fmaf(y3,z.w,MAGIC);
                  y2=__fadd_rn(t0,-MAGIC)*z.x; y3=__fadd_rn(t1,-MAGIC)*z.z; }
                z = zl[2];
                { float t0=fmaf(y4,z.y,MAGIC), t1=fmaf(y5,z.w,MAGIC);
                  y4=__fadd_rn(t0,-MAGIC)*z.x; y5=__fadd_rn(t1,-MAGIC)*z.z; }
                z = zl[3];
                { float t0=fmaf(y6,z.y,MAGIC), t1=fmaf(y7,z.w,MAGIC);
                  y6=__fadd_rn(t0,-MAGIC)*z.x; y7=__fadd_rn(t1,-MAGIC)*z.z; }
            }

            // +128 output shift commutes to DC
            if (r == 0) y0 += 1024.0f;

            IDCT8(y0,y1,y2,y3,y4,y5,y6,y7);   // -> T2[i][l=r]

            __syncwarp();   // all lanes done reading T1 before overwriting
            // T2 store un-transposed: element (i, col l=r) -> position (i, l)
            ub[0*36 + 0*8 + r] = y0;
            ub[0*36 + 1*8 + r] = y1;
            ub[0*36 + 2*8 + r] = y2;
            ub[0*36 + 3*8 + r] = y3;
            ub[1*36 + 0*8 + r] = y4;
            ub[1*36 + 1*8 + r] = y5;
            ub[1*36 + 2*8 + r] = y6;
            ub[1*36 + 3*8 + r] = y7;
            __syncwarp();

            // load my T2 row, row inverse DCT -> spatial pixels
            {
                float4 v0 = *(const float4*)(rp);
                float4 v1 = *(const float4*)(rp + 4);
                x0=v0.x; x1=v0.y; x2=v0.z; x3=v0.w;
                x4=v1.x; x5=v1.y; x6=v1.z; x7=v1.w;
            }
            IDCT8(x0,x1,x2,x3,x4,x5,x6,x7);

            // store pixels over my own row (only THIS lane read it) -> no hazard
            *(float4*)(rp)     = make_float4(x0,x1,x2,x3);
            *(float4*)(rp + 4) = make_float4(x4,x5,x6,x7);
        }
        __syncthreads();

        // ---- Phase C: YCbCr->RGB, clip, store; 512 groups ----
        if (tid < 512) {
            int rr = tid >> 6;
            int cg = tid & 63;
            int col = col0 + (cg << 2);
            int blk = cg >> 1;
            int sb = blk * 72 + (rr >> 2) * 36 + (rr & 3) * 8 + ((cg & 1) << 2);
            float4 y4  = *(const float4*)(sm + sb);
            float4 cb4 = *(const float4*)(sm + 32 * 72 + sb);
            float4 cr4 = *(const float4*)(sm + 64 * 72 + sb);
            float4 ro, go, bo;
            {
                const float* Yp = &y4.x; const float* Cbp = &cb4.x; const float* Crp = &cr4.x;
                float* Rp = &ro.x; float* Gp = &go.x; float* Bp = &bo.x;
                #pragma unroll
                for (int j = 0; j < 4; j++) {
                    float y  = Yp[j];
                    float cb = Cbp[j] - 128.0f;
                    float cr = Crp[j] - 128.0f;
                    float rr2 = y + 1.402f * cr;
                    float gg = y - 0.34414f * cb - 0.71414f * cr;
                    float bb = y + 1.772f * cb;
                    Rp[j] = fminf(fmaxf(rr2 * (1.0f / 255.0f), 0.0f), 1.0f);
                    Gp[j] = fminf(fmaxf(gg * (1.0f / 255.0f), 0.0f), 1.0f);
                    Bp[j] = fminf(fmaxf(bb * (1.0f / 255.0f), 0.0f), 1.0f);
                }
            }
            size_t off = img_base + (size_t)(row0 + rr) * IMG_W + col;
            *(float4*)(out + off)          = ro;
            *(float4*)(out + off + CH)     = go;
            *(float4*)(out + off + 2 * CH) = bo;
        }
    }
}

extern "C" void kernel_launch(void* const* d_in, const int* in_sizes, int n_in,
                              void* d_out, int out_size)
{
    const float* img = (const float*)d_in[0];
    const int* quality = (const int*)d_in[1];
    float* out = (float*)d_out;

    cudaFuncSetAttribute(jpeg_kernel,
                         cudaFuncAttributeMaxDynamicSharedMemorySize,
                         SMEM_BYTES);

    dim3 grid(NRESIDENT);   // 296 persistent CTAs
    jpeg_kernel<<<grid, NTHREADS, SMEM_BYTES>>>(img, quality, out);
}

// round 12
// speedup vs baseline: 1.0947x; 1.0947x over previous
#include <cuda_runtime.h>
#include <math.h>

// DiffJPEG forward: persistent, double-buffered, software-pipelined kernel.
// Octet (8 threads) per 8x8 block; half-strip tasks; zipped quant tables.
// Schedule per task: B(t) | barrier | A(t+1)^buf + C(t) | barrier.
// img: (16,3,512,512) f32, quality: int scalar, out: (16,3,512,512) f32.

#define IMG_W 512
#define IMG_H 512
#define BATCH 16
#define NTHREADS 768
#define NTASKS 2048                        // batch * 64 strips * 2 halves
#define NRESIDENT 296                      // 148 SMs * 2 CTAs
// 96 units (3 ch * 32 blocks); slot = unit*72 + (a>>2)*36 + (a&3)*8 + b
#define BUF_FLOATS (96 * 72)               // 6912
#define SMEM_FLOATS (2 * BUF_FLOATS)       // double buffer
#define SMEM_BYTES  (SMEM_FLOATS * 4)      // 55296

#define MAGIC 12582912.0f                  // 1.5 * 2^23: round-to-nearest-even

#define CA  0.35355339059327373f
#define CB1 0.46193976625564337f
#define CB3 0.19134171618254492f
#define CD1 0.49039264020161522f
#define CD3 0.41573480615127262f
#define CD5 0.27778511650980114f
#define CD7 0.09754516100806413f

#define FDCT8(x0,x1,x2,x3,x4,x5,x6,x7) do {                                  \
    float e0=(x0)+(x7), e1=(x1)+(x6), e2=(x2)+(x5), e3=(x3)+(x4);            \
    float o0=(x0)-(x7), o1=(x1)-(x6), o2=(x2)-(x5), o3=(x3)-(x4);            \
    float ee0=e0+e3, ee1=e1+e2, eo0=e0-e3, eo1=e1-e2;                        \
    (x0) = CA*(ee0+ee1);                                                     \
    (x4) = CA*(ee0-ee1);                                                     \
    (x2) = CB1*eo0 + CB3*eo1;                                                \
    (x6) = CB3*eo0 - CB1*eo1;                                                \
    (x1) = CD1*o0 + CD3*o1 + CD5*o2 + CD7*o3;                                \
    (x3) = CD3*o0 - CD7*o1 - CD1*o2 - CD5*o3;                                \
    (x5) = CD5*o0 - CD1*o1 + CD7*o2 + CD3*o3;                                \
    (x7) = CD7*o0 - CD5*o1 + CD3*o2 - CD1*o3;                                \
} while(0)

#define IDCT8(x0,x1,x2,x3,x4,x5,x6,x7) do {                                  \
    float ee0 = CA*((x0)+(x4)), ee1 = CA*((x0)-(x4));                        \
    float eo0 = CB1*(x2) + CB3*(x6), eo1 = CB3*(x2) - CB1*(x6);              \
    float o0 = CD1*(x1) + CD3*(x3) + CD5*(x5) + CD7*(x7);                    \
    float o1 = CD3*(x1) - CD7*(x3) - CD1*(x5) - CD5*(x7);                    \
    float o2 = CD5*(x1) - CD1*(x3) + CD7*(x5) + CD3*(x7);                    \
    float o3 = CD7*(x1) - CD5*(x3) + CD3*(x5) - CD1*(x7);                    \
    float e0=ee0+eo0, e3=ee0-eo0, e1=ee1+eo1, e2=ee1-eo1;                    \
    (x0)=e0+o0; (x7)=e0-o0; (x1)=e1+o1; (x6)=e1-o1;                          \
    (x2)=e2+o2; (x5)=e2-o2; (x3)=e3+o3; (x4)=e3-o3;                          \
} while(0)

__constant__ float c_lum[64] = {
    16, 11, 10, 16, 24, 40, 51, 61,
    12, 12, 14, 19, 26, 58, 60, 55,
    14, 13, 16, 24, 40, 57, 69, 56,
    14, 17, 22, 29, 51, 87, 80, 62,
    18, 22, 37, 56, 68, 109, 103, 77,
    24, 35, 55, 64, 81, 104, 113, 92,
    49, 64, 78, 87, 103, 121, 120, 101,
    72, 92, 95, 98, 112, 100, 103, 99
};
__constant__ float c_chrom[64] = {
    17, 18, 24, 47, 99, 99, 99, 99,
    18, 21, 26, 66, 99, 99, 99, 99,
    24, 26, 56, 99, 99, 99, 99, 99,
    47, 66, 99, 99, 99, 99, 99, 99,
    99, 99, 99, 99, 99, 99, 99, 99,
    99, 99, 99, 99, 99, 99, 99, 99,
    99, 99, 99, 99, 99, 99, 99, 99,
    99, 99, 99, 99, 99, 99, 99, 99
};

__global__ void __launch_bounds__(NTHREADS, 2)
jpeg_kernel(const float* __restrict__ img,
            const int* __restrict__ quality,
            float* __restrict__ out)
{
    extern __shared__ float sm[];
    __shared__ __align__(16) float qzipL[160];
    __shared__ __align__(16) float qzipC[160];

    const int tid = threadIdx.x;

    if (tid < 256) {
        int t = tid >> 7;
        int rem = tid & 127;
        int l = rem >> 4;
        int kp = (rem >> 2) & 3;
        int comp = rem & 3;
        int k = 2 * kp + (comp >> 1);
        int q = *quality;
        q = max(1, min(100, q));
        float scale = (q < 50) ? (5000.0f / (float)q) : (200.0f - 2.0f * (float)q);
        float base = t ? c_chrom[k * 8 + l] : c_lum[k * 8 + l];
        float v = (base * scale + 50.0f) / 100.0f;
        v = fminf(fmaxf(v, 1.0f), 255.0f);
        float outv = (comp & 1) ? (1.0f / v) : v;
        (t ? qzipC : qzipL)[(l * 5 + kp) * 4 + comp] = outv;
    }

    const size_t CH = (size_t)IMG_H * IMG_W;

    // octet decomposition (task-invariant)
    const int unit = tid >> 3;          // 0..95 = c*32 + blk
    const int r = tid & 7;
    const int c = unit >> 5;
    const int roff = unit * 72 + (r >> 2) * 36 + (r & 3) * 8;

    // A-phase / C-phase decomposition (tid < 512)
    const int arow = tid >> 6;          // 0..7
    const int acg  = tid & 63;          // float4 group
    const int asb  = (acg >> 1) * 72 + (arow >> 2) * 36 + (arow & 3) * 8
                   + ((acg & 1) << 2);

    // ---- Phase A as a lambda (used in prologue and steady state) ----
    auto phaseA = [&](int task, float* buf) {
        if (tid < 512) {
            int b = task >> 7;
            int rem = task & 127;
            int row = (rem >> 1) * 8 + arow;
            int col = ((rem & 1) << 8) + (acg << 2);
            size_t off = (size_t)b * 3 * CH + (size_t)row * IMG_W + col;
            float4 r4 = *(const float4*)(img + off);
            float4 g4 = *(const float4*)(img + off + CH);
            float4 b4 = *(const float4*)(img + off + 2 * CH);
            float4 y4, cb4, cr4;
            const float* Rp = &r4.x; const float* Gp = &g4.x; const float* Bp = &b4.x;
            float* Yp = &y4.x; float* Cbp = &cb4.x; float* Crp = &cr4.x;
            #pragma unroll
            for (int j = 0; j < 4; j++) {
                float R = Rp[j], G = Gp[j], B = Bp[j];
                Yp[j]  = fmaf(76.245f, R, fmaf(149.685f, G, 29.07f * B));
                Cbp[j] = fmaf(-43.0185f, R, fmaf(-84.4815f, G, fmaf(127.5f, B, 128.0f)));
                Crp[j] = fmaf(127.5f, R, fmaf(-106.7685f, G, fmaf(-20.7315f, B, 128.0f)));
            }
            *(float4*)(buf + asb)           = y4;
            *(float4*)(buf + 32 * 72 + asb) = cb4;
            *(float4*)(buf + 64 * 72 + asb) = cr4;
        }
    };

    auto phaseC = [&](int task, const float* buf) {
        if (tid < 512) {
            int b = task >> 7;
            int rem = task & 127;
            int row = (rem >> 1) * 8 + arow;
            int col = ((rem & 1) << 8) + (acg << 2);
            float4 y4  = *(const float4*)(buf + asb);
            float4 cb4 = *(const float4*)(buf + 32 * 72 + asb);
            float4 cr4 = *(const float4*)(buf + 64 * 72 + asb);
            float4 ro, go, bo;
            const float* Yp = &y4.x; const float* Cbp = &cb4.x; const float* Crp = &cr4.x;
            float* Rp = &ro.x; float* Gp = &go.x; float* Bp = &bo.x;
            #pragma unroll
            for (int j = 0; j < 4; j++) {
                float y  = Yp[j];
                float cb = Cbp[j] - 128.0f;
                float cr = Crp[j] - 128.0f;
                float rr = y + 1.402f * cr;
                float gg = y - 0.34414f * cb - 0.71414f * cr;
                float bb = y + 1.772f * cb;
                Rp[j] = fminf(fmaxf(rr * (1.0f / 255.0f), 0.0f), 1.0f);
                Gp[j] = fminf(fmaxf(gg * (1.0f / 255.0f), 0.0f), 1.0f);
                Bp[j] = fminf(fmaxf(bb * (1.0f / 255.0f), 0.0f), 1.0f);
            }
            size_t off = (size_t)b * 3 * CH + (size_t)row * IMG_W + col;
            *(float4*)(out + off)          = ro;
            *(float4*)(out + off + CH)     = go;
            *(float4*)(out + off + 2 * CH) = bo;
        }
    };

    int task = blockIdx.x;
    if (task >= NTASKS) return;

    int p = 0;
    phaseA(task, sm);            // prologue fill of buffer 0
    __syncthreads();             // also orders qzip init

    while (true) {
        float* buf = sm + p * BUF_FLOATS;
        float* const ub = buf + unit * 72;
        float* const rp = buf + roff;

        // ---- Phase B(task): octet per 8x8 block ----
        {
            const int b = task >> 7;
            float x0,x1,x2,x3,x4,x5,x6,x7;
            {
                float4 v0 = *(const float4*)(rp);
                float4 v1 = *(const float4*)(rp + 4);
                x0=v0.x; x1=v0.y; x2=v0.z; x3=v0.w;
                x4=v1.x; x5=v1.y; x6=v1.z; x7=v1.w;
            }
            FDCT8(x0,x1,x2,x3,x4,x5,x6,x7);

            __syncwarp();
            ub[0*36 + 0*8 + r] = x0;
            ub[0*36 + 1*8 + r] = x1;
            ub[0*36 + 2*8 + r] = x2;
            ub[0*36 + 3*8 + r] = x3;
            ub[1*36 + 0*8 + r] = x4;
            ub[1*36 + 1*8 + r] = x5;
            ub[1*36 + 2*8 + r] = x6;
            ub[1*36 + 3*8 + r] = x7;
            __syncwarp();

            float y0,y1,y2,y3,y4,y5,y6,y7;
            {
                float4 v0 = *(const float4*)(rp);
                float4 v1 = *(const float4*)(rp + 4);
                y0=v0.x; y1=v0.y; y2=v0.z; y3=v0.w;
                y4=v1.x; y5=v1.y; y6=v1.z; y7=v1.w;
            }
            FDCT8(y0,y1,y2,y3,y4,y5,y6,y7);

            if (r == 0) y0 -= 1024.0f;     // -128 shift commutes to DC

            {
                const float* qz = ((b * 3 + c) < BATCH) ? qzipL : qzipC;
                const float4* zl = (const float4*)(qz + r * 20);
                float4 z;
                z = zl[0];
                { float t0=fmaf(y0,z.y,MAGIC), t1=fmaf(y1,z.w,MAGIC);
                  y0=__fadd_rn(t0,-MAGIC)*z.x; y1=__fadd_rn(t1,-MAGIC)*z.z; }
                z = zl[1];
                { float t0=fmaf(y2,z.y,MAGIC), t1=fmaf(y3,z.w,MAGIC);
                  y2=__fadd_rn(t0,-MAGIC)*z.x; y3=__fadd_rn(t1,-MAGIC)*z.z; }
                z = zl[2];
                { float t0=fmaf(y4,z.y,MAGIC), t1=fmaf(y5,z.w,MAGIC);
                  y4=__fadd_rn(t0,-MAGIC)*z.x; y5=__fadd_rn(t1,-MAGIC)*z.z; }
                z = zl[3];
                { float t0=fmaf(y6,z.y,MAGIC), t1=fmaf(y7,z.w,MAGIC);
                  y6=__fadd_rn(t0,-MAGIC)*z.x; y7=__fadd_rn(t1,-MAGIC)*z.z; }
            }

            if (r == 0) y0 += 1024.0f;     // +128 shift commutes to DC

            IDCT8(y0,y1,y2,y3,y4,y5,y6,y7);

            __syncwarp();
            ub[0*36 + 0*8 + r] = y0;
            ub[0*36 + 1*8 + r] = y1;
            ub[0*36 + 2*8 + r] = y2;
            ub[0*36 + 3*8 + r] = y3;
            ub[1*36 + 0*8 + r] = y4;
            ub[1*36 + 1*8 + r] = y5;
            ub[1*36 + 2*8 + r] = y6;
            ub[1*36 + 3*8 + r] = y7;
            __syncwarp();

            {
                float4 v0 = *(const float4*)(rp);
                float4 v1 = *(const float4*)(rp + 4);
                x0=v0.x; x1=v0.y; x2=v0.z; x3=v0.w;
                x4=v1.x; x5=v1.y; x6=v1.z; x7=v1.w;
            }
            IDCT8(x0,x1,x2,x3,x4,x5,x6,x7);

            *(float4*)(rp)     = make_float4(x0,x1,x2,x3);
            *(float4*)(rp + 4) = make_float4(x4,x5,x6,x7);
        }
        __syncthreads();

        // ---- A(next task) into the other buffer, then C(task) ----
        int tn = task + NRESIDENT;
        if (tn < NTASKS) {
            phaseA(tn, sm + (p ^ 1) * BUF_FLOATS);   // LDGs issued early
            phaseC(task, buf);
            task = tn;
            p ^= 1;
            __syncthreads();     // A stores visible before B(tn); C reads done
        } else {
            phaseC(task, buf);
            break;
        }
    }
}

extern "C" void kernel_launch(void* const* d_in, const int* in_sizes, int n_in,
                              void* d_out, int out_size)
{
    const float* img = (const float*)d_in[0];
    const int* quality = (const int*)d_in[1];
    float* out = (float*)d_out;

    cudaFuncSetAttribute(jpeg_kernel,
                         cudaFuncAttributeMaxDynamicSharedMemorySize,
                         SMEM_BYTES);

    dim3 grid(NRESIDENT);   // 296 persistent CTAs
    jpeg_kernel<<<grid, NTHREADS, SMEM_BYTES>>>(img, quality, out);
}